// round 15
// baseline (speedup 1.0000x reference)
#include <cuda_runtime.h>
#include <cuda_fp16.h>
#include <math.h>
#include <stdint.h>

#define N_I 100000
#define N_O 50000
#define FD 32
#define EAD 8
#define NE 100000

// Scratch (allocation-free): accumulators, reused in-place as h after root+sigmoid.
__device__ __align__(16) float g_acc_i[N_I * FD];   // layer-1 indivi agg -> h_indivi
__device__ __align__(16) float g_acc_o[N_O * FD];   // layer-1 org agg    -> h_org
__device__ __align__(16) float g_acc2[N_I];         // layer-2 agg

__device__ __forceinline__ float sigmoidf(float v) {
    return 1.0f / (1.0f + expf(-v));
}

__device__ __forceinline__ uint32_t packh2(float lo, float hi) {
    __half2 h = __floats2half2_rn(lo, hi);
    return *(uint32_t*)&h;
}
__device__ __forceinline__ uint32_t h2splat(float v) {
    __half2 h = __floats2half2_rn(v, v);
    return *(uint32_t*)&h;
}
__device__ __forceinline__ uint32_t hmul2u(uint32_t a, uint32_t b) {
    __half2 r = __hmul2(*(__half2*)&a, *(__half2*)&b);
    return *(uint32_t*)&r;
}

// m16n8k16 f16 HMMA, f32 accumulate (base-target PTX, sm_80+).
__device__ __forceinline__ void mma16n8k16(float* d, const uint32_t* a,
                                           uint32_t b0, uint32_t b1) {
    asm volatile(
        "mma.sync.aligned.m16n8k16.row.col.f32.f16.f16.f32 "
        "{%0,%1,%2,%3}, {%4,%5,%6,%7}, {%8,%9}, {%0,%1,%2,%3};"
        : "+f"(d[0]), "+f"(d[1]), "+f"(d[2]), "+f"(d[3])
        : "r"(a[0]), "r"(a[1]), "r"(a[2]), "r"(a[3]), "r"(b0), "r"(b1));
}

// ---------------------------------------------------------------------------
// Zero kernels, split in 3 so edge_mma lands in the ncu capture slot (4th).
// ---------------------------------------------------------------------------
__global__ void zero_i_kernel() {
    const float4 z = make_float4(0.f, 0.f, 0.f, 0.f);
    int idx = blockIdx.x * blockDim.x + threadIdx.x;
    int stride = gridDim.x * blockDim.x;
    for (int i = idx; i < N_I * FD / 4; i += stride) ((float4*)g_acc_i)[i] = z;
}
__global__ void zero_o_kernel() {
    const float4 z = make_float4(0.f, 0.f, 0.f, 0.f);
    int idx = blockIdx.x * blockDim.x + threadIdx.x;
    int stride = gridDim.x * blockDim.x;
    for (int i = idx; i < N_O * FD / 4; i += stride) ((float4*)g_acc_o)[i] = z;
}
__global__ void zero_a2_kernel() {
    const float4 z = make_float4(0.f, 0.f, 0.f, 0.f);
    int idx = blockIdx.x * blockDim.x + threadIdx.x;
    int stride = gridDim.x * blockDim.x;
    for (int i = idx; i < N_I / 4; i += stride) ((float4*)g_acc2)[i] = z;
}

// ---------------------------------------------------------------------------
// Layer-1 edge kernel via mma.sync m16n8k16.f16 (f32 accumulate).
//   msg[e,o] = sum_c (s_c[e]*x[src[e],:]) @ Wc,  s_0=1 (bm), s_{1+a}=ea[e,a]
// (R10/R12 body = best measured config)
// ---------------------------------------------------------------------------
#define ECTA 1024
#define EDGE_CTAS_PER_REL ((NE + ECTA - 1) / ECTA)   // 98

#define SXS2 20
#define SWS2 40
#define SCS  12
#define SW2_BYTES (144 * SWS2 * 4)            // 23040
#define SX2_BYTES (32 * SXS2 * 4)             // 2560 per warp
#define SC2_BYTES (32 * SCS * 4)              // 1536 per warp
#define OFF_SX2  SW2_BYTES                    // 23040
#define OFF_SC2  (OFF_SX2 + 8 * SX2_BYTES)    // 43520
#define SMEM_DYN (OFF_SC2 + 8 * SC2_BYTES)    // 55808

__global__ __launch_bounds__(256) void edge_mma_kernel(
    const float* __restrict__ xA, const int* __restrict__ srcA,
    const int* __restrict__ dstA, const float* __restrict__ eaA,
    const float* __restrict__ WmA, const float* __restrict__ bmA,
    const float* __restrict__ xB, const int* __restrict__ srcB,
    const int* __restrict__ dstB, const float* __restrict__ eaB,
    const float* __restrict__ WmB, const float* __restrict__ bmB)
{
    extern __shared__ char smem[];
    uint32_t* sW = (uint32_t*)smem;                      // [144][40] half2 k-pairs

    const int rel  = (blockIdx.x >= EDGE_CTAS_PER_REL) ? 1 : 0;
    const int tile = blockIdx.x - rel * EDGE_CTAS_PER_REL;

    const float* __restrict__ x   = rel ? xB   : xA;
    const int*   __restrict__ src = rel ? srcB : srcA;
    const int*   __restrict__ dst = rel ? dstB : dstA;
    const float* __restrict__ ea  = rel ? eaB  : eaA;
    const float* __restrict__ Wm  = rel ? WmB  : WmA;
    const float* __restrict__ bm  = rel ? bmB  : bmA;
    float* acc = rel ? g_acc_o : g_acc_i;

    const int t = threadIdx.x;
    const int warp = t >> 5;
    const int lane = t & 31;
    const int g   = lane >> 2;   // fragment row group 0..7
    const int tig = lane & 3;    // thread-in-group 0..3

    // ---- stage W' = [bm ; Wm] as half2 k-pairs: sW[kp][n], kp = k/2 ----
    for (int idx = t; idx < 144 * 32; idx += 256) {
        int kp = idx >> 5, n = idx & 31;
        int k0 = 2 * kp, k1 = k0 + 1;
        float v0 = (k0 < 32) ? bm[k0 * 32 + n] : Wm[(k0 - 32) * 32 + n];
        float v1 = (k1 < 32) ? bm[k1 * 32 + n] : Wm[(k1 - 32) * 32 + n];
        sW[kp * SWS2 + n] = packh2(v0, v1);
    }
    __syncthreads();

    uint32_t* sx  = (uint32_t*)(smem + OFF_SX2 + warp * SX2_BYTES);  // [32][20]
    float*    ssc = (float*)   (smem + OFF_SC2 + warp * SC2_BYTES);  // [32][12]

    const int cta_e0 = tile * ECTA;
    const int h2 = lane >> 4;    // half-warp id for staging
    const int p2 = lane & 15;    // col-pair id for staging

    for (int pp = 0; pp < 4; pp++) {
        const int e0 = cta_e0 + warp * 128 + pp * 32;
        const int e_l = e0 + lane;
        const bool v_l = (e_l < NE);
        const int src_l = v_l ? src[e_l] : 0;
        const int dst_l = v_l ? dst[e_l] : -1;

        __syncwarp();
        // ---- stage scales: row r -> [1, ea0..ea7] ----
        {
            float4 q0 = make_float4(0.f,0.f,0.f,0.f), q1 = q0;
            if (v_l) { q0 = ((const float4*)ea)[e_l * 2]; q1 = ((const float4*)ea)[e_l * 2 + 1]; }
            float* sr = ssc + lane * SCS;
            sr[0] = 1.f;
            sr[1] = q0.x; sr[2] = q0.y; sr[3] = q0.z; sr[4] = q0.w;
            sr[5] = q1.x; sr[6] = q1.y; sr[7] = q1.z; sr[8] = q1.w;
        }
        // ---- stage x rows as half2 pairs (2 rows per iteration, coalesced) ----
        #pragma unroll 4
        for (int rr = 0; rr < 16; rr++) {
            const int row = 2 * rr + h2;
            const int s_r = __shfl_sync(0xffffffffu, src_l, row);
            const float2 v = *(const float2*)(x + (size_t)s_r * FD + 2 * p2);
            sx[row * SXS2 + p2] = packh2(v.x, v.y);
        }
        __syncwarp();

        // ---- base A fragments: 2 strips x 2 k16-steps x 4 regs ----
        uint32_t A[2][2][4];
        #pragma unroll
        for (int s = 0; s < 2; s++) {
            #pragma unroll
            for (int ks = 0; ks < 2; ks++) {
                const int rb = s * 16 + g, kp = ks * 8;
                A[s][ks][0] = sx[rb * SXS2 + kp + tig];
                A[s][ks][1] = sx[(rb + 8) * SXS2 + kp + tig];
                A[s][ks][2] = sx[rb * SXS2 + kp + tig + 4];
                A[s][ks][3] = sx[(rb + 8) * SXS2 + kp + tig + 4];
            }
        }
        int dlo[2], dhi[2];
        dlo[0] = __shfl_sync(0xffffffffu, dst_l, g);
        dhi[0] = __shfl_sync(0xffffffffu, dst_l, g + 8);
        dlo[1] = __shfl_sync(0xffffffffu, dst_l, g + 16);
        dhi[1] = __shfl_sync(0xffffffffu, dst_l, g + 24);

        float m[4][2][4] = {};   // [nt][strip][4] accumulators

        #pragma unroll
        for (int c = 0; c < 9; c++) {
            const uint32_t sl0 = h2splat(ssc[(g)      * SCS + c]);
            const uint32_t sh0 = h2splat(ssc[(g + 8)  * SCS + c]);
            const uint32_t sl1 = h2splat(ssc[(g + 16) * SCS + c]);
            const uint32_t sh1 = h2splat(ssc[(g + 24) * SCS + c]);

            uint32_t As[2][2][4];
            #pragma unroll
            for (int ks = 0; ks < 2; ks++) {
                As[0][ks][0] = hmul2u(A[0][ks][0], sl0);
                As[0][ks][1] = hmul2u(A[0][ks][1], sh0);
                As[0][ks][2] = hmul2u(A[0][ks][2], sl0);
                As[0][ks][3] = hmul2u(A[0][ks][3], sh0);
                As[1][ks][0] = hmul2u(A[1][ks][0], sl1);
                As[1][ks][1] = hmul2u(A[1][ks][1], sh1);
                As[1][ks][2] = hmul2u(A[1][ks][2], sl1);
                As[1][ks][3] = hmul2u(A[1][ks][3], sh1);
            }

            #pragma unroll
            for (int nt = 0; nt < 4; nt++) {
                const int nb = nt * 8 + g;
                #pragma unroll
                for (int ks = 0; ks < 2; ks++) {
                    const int kpb = c * 16 + ks * 8;
                    const uint32_t b0 = sW[(kpb + tig) * SWS2 + nb];
                    const uint32_t b1 = sW[(kpb + tig + 4) * SWS2 + nb];
                    mma16n8k16(m[nt][0], As[0][ks], b0, b1);
                    mma16n8k16(m[nt][1], As[1][ks], b0, b1);
                }
            }
        }

        // ---- epilogue: pair-exchange -> one float4 RED per thread per strip ----
        #pragma unroll
        for (int nt = 0; nt < 4; nt++) {
            const int colb = nt * 8 + 2 * (tig & ~1);
            const bool odd = (tig & 1);
            #pragma unroll
            for (int s = 0; s < 2; s++) {
                float s0 = __shfl_xor_sync(0xffffffffu, odd ? m[nt][s][0] : m[nt][s][2], 1);
                float s1 = __shfl_xor_sync(0xffffffffu, odd ? m[nt][s][1] : m[nt][s][3], 1);
                int drow = odd ? dhi[s] : dlo[s];
                float4 val = odd ? make_float4(s0, s1, m[nt][s][2], m[nt][s][3])
                                 : make_float4(m[nt][s][0], m[nt][s][1], s0, s1);
                if (drow >= 0)
                    atomicAdd((float4*)(acc + (size_t)drow * FD + colb), val);
            }
        }
    }
}

// ---------------------------------------------------------------------------
// Root kernel via mma.sync m16n8k16.f16, COALESCED epilogue:
//   acc[n,:] = sigmoid(acc[n,:] + x[n,:] @ Wr + b)
// MMA as R14; then c-fragments staged to per-warp smem tile [32][36] and the
// acc RMW done row-major (float4 per lane, full 128B transactions). The x
// staging buffer is dead after fragment load, so the result tile overlays it.
// ---------------------------------------------------------------------------
#define ROOT_BLK_I ((N_I + 255) / 256)   // 391
#define ROOT_BLK_O ((N_O + 255) / 196)   // placeholder (unused)
#undef ROOT_BLK_O
#define ROOT_BLK_O ((N_O + 255) / 256)   // 196

#define RSF 36                                  // result-tile stride (floats)
#define R_OFF_SB   0                            // sB: 16*SWS2 u32 = 2560B
#define R_OFF_BIAS (16 * SWS2 * 4)              // 2560
#define R_OFF_WARP (R_OFF_BIAS + 128)           // 2688
#define R_WARP_BYTES (32 * RSF * 4)             // 4608 (sx 2560B overlays this)
#define ROOT_SMEM  (R_OFF_WARP + 8 * R_WARP_BYTES)  // 39552

__global__ __launch_bounds__(256) void root_mma(
    const float* __restrict__ xI, const float* __restrict__ WrI, const float* __restrict__ bI,
    const float* __restrict__ xO, const float* __restrict__ WrO, const float* __restrict__ bO)
{
    extern __shared__ char rsmem[];
    uint32_t* sB = (uint32_t*)(rsmem + R_OFF_SB);
    float*    sb = (float*)   (rsmem + R_OFF_BIAS);

    const int rel = (blockIdx.x >= ROOT_BLK_I) ? 1 : 0;
    const float* __restrict__ x  = rel ? xO  : xI;
    const float* __restrict__ Wr = rel ? WrO : WrI;
    const float* __restrict__ b  = rel ? bO  : bI;
    float* acc = rel ? g_acc_o : g_acc_i;
    const int N = rel ? N_O : N_I;
    const int base = (rel ? (blockIdx.x - ROOT_BLK_I) : blockIdx.x) * 256;

    const int t = threadIdx.x;
    const int warp = t >> 5;
    const int lane = t & 31;
    const int g   = lane >> 2;
    const int tig = lane & 3;

    // stage Wr (B matrix) + bias (grid-stride over 512 entries)
    for (int idx = t; idx < 512; idx += 256) {
        int kp = idx >> 5, n = idx & 31;
        sB[kp * SWS2 + n] = packh2(Wr[(2 * kp) * FD + n], Wr[(2 * kp + 1) * FD + n]);
    }
    if (t < FD) sb[t] = b[t];
    __syncthreads();

    const int rowbase = base + warp * 32;
    float*    sf = (float*)(rsmem + R_OFF_WARP + warp * R_WARP_BYTES);  // [32][36]
    uint32_t* sx = (uint32_t*)sf;                                       // overlay [32][20]
    const int h2 = lane >> 4;
    const int p2 = lane & 15;

    // ---- stage x rows as half2 (contiguous rows, coalesced 128B) ----
    #pragma unroll 4
    for (int rr = 0; rr < 16; rr++) {
        const int row = 2 * rr + h2;
        const int gn = rowbase + row;
        float2 v = make_float2(0.f, 0.f);
        if (gn < N) v = *(const float2*)(x + (size_t)gn * FD + 2 * p2);
        sx[row * SXS2 + p2] = packh2(v.x, v.y);
    }
    __syncwarp();

    // ---- A fragments: 2 strips x 2 k16-steps ----
    uint32_t A[2][2][4];
    #pragma unroll
    for (int s = 0; s < 2; s++) {
        #pragma unroll
        for (int ks = 0; ks < 2; ks++) {
            const int rb = s * 16 + g, kp = ks * 8;
            A[s][ks][0] = sx[rb * SXS2 + kp + tig];
            A[s][ks][1] = sx[(rb + 8) * SXS2 + kp + tig];
            A[s][ks][2] = sx[rb * SXS2 + kp + tig + 4];
            A[s][ks][3] = sx[(rb + 8) * SXS2 + kp + tig + 4];
        }
    }
    __syncwarp();   // sx fully consumed; sf may now be overwritten

    float m[4][2][4] = {};
    #pragma unroll
    for (int nt = 0; nt < 4; nt++) {
        const int nb = nt * 8 + g;
        #pragma unroll
        for (int ks = 0; ks < 2; ks++) {
            const uint32_t b0 = sB[(ks * 8 + tig) * SWS2 + nb];
            const uint32_t b1 = sB[(ks * 8 + tig + 4) * SWS2 + nb];
            mma16n8k16(m[nt][0], A[0][ks], b0, b1);
            mma16n8k16(m[nt][1], A[1][ks], b0, b1);
        }
    }

    // ---- stage fragments into result tile ----
    #pragma unroll
    for (int nt = 0; nt < 4; nt++) {
        const int colb = nt * 8 + 2 * tig;
        #pragma unroll
        for (int s = 0; s < 2; s++) {
            const int r0 = s * 16 + g, r1 = r0 + 8;
            *(float2*)(sf + r0 * RSF + colb) = make_float2(m[nt][s][0], m[nt][s][1]);
            *(float2*)(sf + r1 * RSF + colb) = make_float2(m[nt][s][2], m[nt][s][3]);
        }
    }
    __syncwarp();

    // ---- coalesced RMW: lane covers (row 4*r8 + l>>3, cols (l&7)*4 .. +3) ----
    const int rloc = lane >> 3;
    const int cq   = (lane & 7) * 4;
    const float4 bq = ((const float4*)sb)[lane & 7];
    #pragma unroll
    for (int r8 = 0; r8 < 8; r8++) {
        const int row = r8 * 4 + rloc;
        const int gn = rowbase + row;
        if (gn < N) {
            float4* p = (float4*)(acc + (size_t)gn * FD + cq);
            float4 av = *p;
            const float4 mv = *(const float4*)(sf + row * RSF + cq);
            av.x = sigmoidf(av.x + mv.x + bq.x);
            av.y = sigmoidf(av.y + mv.y + bq.y);
            av.z = sigmoidf(av.z + mv.z + bq.z);
            av.w = sigmoidf(av.w + mv.w + bq.w);
            *p = av;
        }
    }
}

// ---------------------------------------------------------------------------
// Layer-2 edge kernel (f_out = 1), 8 edges per warp, 2 per octet (MLP=2)
// (R9 version: measured 10.0 us, 32 regs)
// ---------------------------------------------------------------------------
__global__ __launch_bounds__(256) void edge2_kernel(
    const int*   __restrict__ src,
    const int*   __restrict__ dst,
    const float* __restrict__ eattr,
    const float* __restrict__ Wm2,
    const float* __restrict__ bm2)
{
    __shared__ float4 sW4[EAD * 8];
    __shared__ float4 sb4[8];

    const int t = threadIdx.x;
    if (t < EAD * 8) sW4[t] = ((const float4*)Wm2)[t];
    if (t < 8)       sb4[t] = ((const float4*)bm2)[t];
    __syncthreads();

    const int gwarp = (blockIdx.x * 256 + t) >> 5;
    const int lane  = t & 31;
    const int q     = lane & 7;
    const int e1    = gwarp * 8 + (lane >> 3);
    const int e2    = e1 + 4;
    if (e1 >= NE) return;
    const bool v2 = (e2 < NE);

    const int s1 = src[e1];
    const int s2 = v2 ? src[e2] : 0;
    const float4 h1 = ((const float4*)g_acc_o)[s1 * 8 + q];
    const float4 h2 = ((const float4*)g_acc_o)[s2 * 8 + q];
    const float4 a10 = ((const float4*)eattr)[e1 * 2 + 0];
    const float4 a11 = ((const float4*)eattr)[e1 * 2 + 1];
    const float4 a20 = v2 ? ((const float4*)eattr)[e2 * 2 + 0] : make_float4(0,0,0,0);
    const float4 a21 = v2 ? ((const float4*)eattr)[e2 * 2 + 1] : make_float4(0,0,0,0);
    const float ea1[EAD] = {a10.x, a10.y, a10.z, a10.w, a11.x, a11.y, a11.z, a11.w};
    const float ea2[EAD] = {a20.x, a20.y, a20.z, a20.w, a21.x, a21.y, a21.z, a21.w};

    float4 c1 = sb4[q], c2 = sb4[q];
    #pragma unroll
    for (int a = 0; a < EAD; a++) {
        const float4 w = sW4[a * 8 + q];
        c1.x = fmaf(ea1[a], w.x, c1.x);  c2.x = fmaf(ea2[a], w.x, c2.x);
        c1.y = fmaf(ea1[a], w.y, c1.y);  c2.y = fmaf(ea2[a], w.y, c2.y);
        c1.z = fmaf(ea1[a], w.z, c1.z);  c2.z = fmaf(ea2[a], w.z, c2.z);
        c1.w = fmaf(ea1[a], w.w, c1.w);  c2.w = fmaf(ea2[a], w.w, c2.w);
    }

    float p1 = h1.x * c1.x + h1.y * c1.y + h1.z * c1.z + h1.w * c1.w;
    float p2 = h2.x * c2.x + h2.y * c2.y + h2.z * c2.z + h2.w * c2.w;
    p1 += __shfl_down_sync(0xffffffffu, p1, 4, 8);
    p2 += __shfl_down_sync(0xffffffffu, p2, 4, 8);
    p1 += __shfl_down_sync(0xffffffffu, p1, 2, 8);
    p2 += __shfl_down_sync(0xffffffffu, p2, 2, 8);
    p1 += __shfl_down_sync(0xffffffffu, p1, 1, 8);
    p2 += __shfl_down_sync(0xffffffffu, p2, 1, 8);

    if (q == 0) {
        atomicAdd(&g_acc2[dst[e1]], p1);
        if (v2) atomicAdd(&g_acc2[dst[e2]], p2);
    }
}

// ---------------------------------------------------------------------------
// Output: out[n] = sigmoid(acc2[n] + h_indivi[n,:] @ Wr2 + b2)   (warp per node)
// ---------------------------------------------------------------------------
__global__ __launch_bounds__(256) void out_kernel(
    const float* __restrict__ Wr2,
    const float* __restrict__ b2,
    float* __restrict__ out)
{
    const int t = threadIdx.x;
    const int n = (blockIdx.x * 256 + t) >> 5;
    const int lane = t & 31;
    if (n >= N_I) return;

    float p = g_acc_i[n * FD + lane] * __ldg(&Wr2[lane]);
    #pragma unroll
    for (int off = 16; off; off >>= 1)
        p += __shfl_down_sync(0xffffffffu, p, off);

    if (lane == 0)
        out[n] = sigmoidf(p + g_acc2[n] + __ldg(&b2[0]));
}

// ---------------------------------------------------------------------------
extern "C" void kernel_launch(void* const* d_in, const int* in_sizes, int n_in,
                              void* d_out, int out_size)
{
    const float* x_indivi = (const float*)d_in[0];
    const float* x_org    = (const float*)d_in[1];
    const int*   src_oi   = (const int*)  d_in[2];
    const int*   dst_oi   = (const int*)  d_in[3];
    const float* ea_oi    = (const float*)d_in[4];
    const int*   src_io   = (const int*)  d_in[5];
    const int*   dst_io   = (const int*)  d_in[6];
    const float* ea_io    = (const float*)d_in[7];
    const float* Wm_oi    = (const float*)d_in[8];
    const float* bm_oi    = (const float*)d_in[9];
    const float* Wr_oi    = (const float*)d_in[10];
    const float* b_oi     = (const float*)d_in[11];
    const float* Wm_io    = (const float*)d_in[12];
    const float* bm_io    = (const float*)d_in[13];
    const float* Wr_io    = (const float*)d_in[14];
    const float* b_io     = (const float*)d_in[15];
    const float* Wm2      = (const float*)d_in[16];
    const float* bm2      = (const float*)d_in[17];
    const float* Wr2      = (const float*)d_in[18];
    const float* b2       = (const float*)d_in[19];
    float* out = (float*)d_out;

    cudaFuncSetAttribute(edge_mma_kernel,
                         cudaFuncAttributeMaxDynamicSharedMemorySize, SMEM_DYN);

    // Launch order: edge_mma is the 4th kernel = the ncu capture slot.
    zero_i_kernel<<<256, 256>>>();
    zero_o_kernel<<<128, 256>>>();
    zero_a2_kernel<<<64, 256>>>();
    // rel0 (org->indivi): src=x_org, acc=g_acc_i. rel1 (indivi->org): src=x_indivi, acc=g_acc_o.
    edge_mma_kernel<<<2 * EDGE_CTAS_PER_REL, 256, SMEM_DYN>>>(
        x_org,    src_oi, dst_oi, ea_oi, Wm_oi, bm_oi,
        x_indivi, src_io, dst_io, ea_io, Wm_io, bm_io);
    root_mma<<<ROOT_BLK_I + ROOT_BLK_O, 256, ROOT_SMEM>>>(
        x_indivi, Wr_oi, b_oi, x_org, Wr_io, b_io);
    edge2_kernel<<<(NE + 8 * 8 - 1) / (8 * 8), 256>>>(src_oi, dst_oi, ea_oi, Wm2, bm2);
    out_kernel<<<(N_I * 32 + 255) / 256, 256>>>(Wr2, b2, out);
}

// round 16
// speedup vs baseline: 1.1021x; 1.1021x over previous
#include <cuda_runtime.h>
#include <cuda_fp16.h>
#include <math.h>
#include <stdint.h>

#define N_I 100000
#define N_O 50000
#define FD 32
#define EAD 8
#define NE 100000

// Scratch (allocation-free): accumulators, reused in-place as h after root+sigmoid.
__device__ __align__(16) float g_acc_i[N_I * FD];   // layer-1 indivi agg -> h_indivi
__device__ __align__(16) float g_acc_o[N_O * FD];   // layer-1 org agg    -> h_org
__device__ __align__(16) float g_acc2[N_I];         // layer-2 agg

__device__ __forceinline__ float sigmoidf(float v) {
    return 1.0f / (1.0f + expf(-v));
}

__device__ __forceinline__ uint32_t packh2(float lo, float hi) {
    __half2 h = __floats2half2_rn(lo, hi);
    return *(uint32_t*)&h;
}
__device__ __forceinline__ uint32_t h2splat(float v) {
    __half2 h = __floats2half2_rn(v, v);
    return *(uint32_t*)&h;
}
__device__ __forceinline__ uint32_t hmul2u(uint32_t a, uint32_t b) {
    __half2 r = __hmul2(*(__half2*)&a, *(__half2*)&b);
    return *(uint32_t*)&r;
}

// m16n8k16 f16 HMMA, f32 accumulate (base-target PTX, sm_80+).
__device__ __forceinline__ void mma16n8k16(float* d, const uint32_t* a,
                                           uint32_t b0, uint32_t b1) {
    asm volatile(
        "mma.sync.aligned.m16n8k16.row.col.f32.f16.f16.f32 "
        "{%0,%1,%2,%3}, {%4,%5,%6,%7}, {%8,%9}, {%0,%1,%2,%3};"
        : "+f"(d[0]), "+f"(d[1]), "+f"(d[2]), "+f"(d[3])
        : "r"(a[0]), "r"(a[1]), "r"(a[2]), "r"(a[3]), "r"(b0), "r"(b1));
}

// ---------------------------------------------------------------------------
// Zero all accumulators (float4 grid-stride, single launch)
// ---------------------------------------------------------------------------
__global__ void zero_kernel() {
    const float4 z = make_float4(0.f, 0.f, 0.f, 0.f);
    int idx = blockIdx.x * blockDim.x + threadIdx.x;
    int stride = gridDim.x * blockDim.x;
    for (int i = idx; i < N_I * FD / 4; i += stride) ((float4*)g_acc_i)[i] = z;
    for (int i = idx; i < N_O * FD / 4; i += stride) ((float4*)g_acc_o)[i] = z;
    for (int i = idx; i < N_I / 4;      i += stride) ((float4*)g_acc2)[i] = z;
}

// ---------------------------------------------------------------------------
// Layer-1 edge kernel via mma.sync m16n8k16.f16 (f32 accumulate).
//   msg[e,o] = sum_c (s_c[e]*x[src[e],:]) @ Wc,  s_0=1 (bm), s_{1+a}=ea[e,a]
// R16: ECTA=256 (one 32-edge pair per warp) -> grid 784 CTAs = 5.3/SM,
// fixing the R15-measured occupancy starvation (196 CTAs -> occ 15.7%).
// ---------------------------------------------------------------------------
#define ECTA 256
#define EDGE_CTAS_PER_REL ((NE + ECTA - 1) / ECTA)   // 391

#define SXS2 20
#define SWS2 40
#define SCS  12
#define SW2_BYTES (144 * SWS2 * 4)            // 23040
#define SX2_BYTES (32 * SXS2 * 4)             // 2560 per warp
#define SC2_BYTES (32 * SCS * 4)              // 1536 per warp
#define OFF_SX2  SW2_BYTES                    // 23040
#define OFF_SC2  (OFF_SX2 + 8 * SX2_BYTES)    // 43520
#define SMEM_DYN (OFF_SC2 + 8 * SC2_BYTES)    // 55808

__global__ __launch_bounds__(256) void edge_mma_kernel(
    const float* __restrict__ xA, const int* __restrict__ srcA,
    const int* __restrict__ dstA, const float* __restrict__ eaA,
    const float* __restrict__ WmA, const float* __restrict__ bmA,
    const float* __restrict__ xB, const int* __restrict__ srcB,
    const int* __restrict__ dstB, const float* __restrict__ eaB,
    const float* __restrict__ WmB, const float* __restrict__ bmB)
{
    extern __shared__ char smem[];
    uint32_t* sW = (uint32_t*)smem;                      // [144][40] half2 k-pairs

    const int rel  = (blockIdx.x >= EDGE_CTAS_PER_REL) ? 1 : 0;
    const int tile = blockIdx.x - rel * EDGE_CTAS_PER_REL;

    const float* __restrict__ x   = rel ? xB   : xA;
    const int*   __restrict__ src = rel ? srcB : srcA;
    const int*   __restrict__ dst = rel ? dstB : dstA;
    const float* __restrict__ ea  = rel ? eaB  : eaA;
    const float* __restrict__ Wm  = rel ? WmB  : WmA;
    const float* __restrict__ bm  = rel ? bmB  : bmA;
    float* acc = rel ? g_acc_o : g_acc_i;

    const int t = threadIdx.x;
    const int warp = t >> 5;
    const int lane = t & 31;
    const int g   = lane >> 2;   // fragment row group 0..7
    const int tig = lane & 3;    // thread-in-group 0..3

    // ---- stage W' = [bm ; Wm] as half2 k-pairs: sW[kp][n], kp = k/2 ----
    for (int idx = t; idx < 144 * 32; idx += 256) {
        int kp = idx >> 5, n = idx & 31;
        int k0 = 2 * kp, k1 = k0 + 1;
        float v0 = (k0 < 32) ? bm[k0 * 32 + n] : Wm[(k0 - 32) * 32 + n];
        float v1 = (k1 < 32) ? bm[k1 * 32 + n] : Wm[(k1 - 32) * 32 + n];
        sW[kp * SWS2 + n] = packh2(v0, v1);
    }
    __syncthreads();

    uint32_t* sx  = (uint32_t*)(smem + OFF_SX2 + warp * SX2_BYTES);  // [32][20]
    float*    ssc = (float*)   (smem + OFF_SC2 + warp * SC2_BYTES);  // [32][12]

    const int h2 = lane >> 4;    // half-warp id for staging
    const int p2 = lane & 15;    // col-pair id for staging

    const int e0 = tile * ECTA + warp * 32;
    const int e_l = e0 + lane;
    const bool v_l = (e_l < NE);
    const int src_l = v_l ? src[e_l] : 0;
    const int dst_l = v_l ? dst[e_l] : -1;

    // ---- stage scales: row r -> [1, ea0..ea7] ----
    {
        float4 q0 = make_float4(0.f,0.f,0.f,0.f), q1 = q0;
        if (v_l) { q0 = ((const float4*)ea)[e_l * 2]; q1 = ((const float4*)ea)[e_l * 2 + 1]; }
        float* sr = ssc + lane * SCS;
        sr[0] = 1.f;
        sr[1] = q0.x; sr[2] = q0.y; sr[3] = q0.z; sr[4] = q0.w;
        sr[5] = q1.x; sr[6] = q1.y; sr[7] = q1.z; sr[8] = q1.w;
    }
    // ---- stage x rows as half2 pairs (2 rows per iteration, coalesced) ----
    #pragma unroll 4
    for (int rr = 0; rr < 16; rr++) {
        const int row = 2 * rr + h2;
        const int s_r = __shfl_sync(0xffffffffu, src_l, row);
        const float2 v = *(const float2*)(x + (size_t)s_r * FD + 2 * p2);
        sx[row * SXS2 + p2] = packh2(v.x, v.y);
    }
    __syncwarp();

    // ---- base A fragments: 2 strips x 2 k16-steps x 4 regs ----
    uint32_t A[2][2][4];
    #pragma unroll
    for (int s = 0; s < 2; s++) {
        #pragma unroll
        for (int ks = 0; ks < 2; ks++) {
            const int rb = s * 16 + g, kp = ks * 8;
            A[s][ks][0] = sx[rb * SXS2 + kp + tig];
            A[s][ks][1] = sx[(rb + 8) * SXS2 + kp + tig];
            A[s][ks][2] = sx[rb * SXS2 + kp + tig + 4];
            A[s][ks][3] = sx[(rb + 8) * SXS2 + kp + tig + 4];
        }
    }
    int dlo[2], dhi[2];
    dlo[0] = __shfl_sync(0xffffffffu, dst_l, g);
    dhi[0] = __shfl_sync(0xffffffffu, dst_l, g + 8);
    dlo[1] = __shfl_sync(0xffffffffu, dst_l, g + 16);
    dhi[1] = __shfl_sync(0xffffffffu, dst_l, g + 24);

    float m[4][2][4] = {};   // [nt][strip][4] accumulators

    #pragma unroll
    for (int c = 0; c < 9; c++) {
        const uint32_t sl0 = h2splat(ssc[(g)      * SCS + c]);
        const uint32_t sh0 = h2splat(ssc[(g + 8)  * SCS + c]);
        const uint32_t sl1 = h2splat(ssc[(g + 16) * SCS + c]);
        const uint32_t sh1 = h2splat(ssc[(g + 24) * SCS + c]);

        uint32_t As[2][2][4];
        #pragma unroll
        for (int ks = 0; ks < 2; ks++) {
            As[0][ks][0] = hmul2u(A[0][ks][0], sl0);
            As[0][ks][1] = hmul2u(A[0][ks][1], sh0);
            As[0][ks][2] = hmul2u(A[0][ks][2], sl0);
            As[0][ks][3] = hmul2u(A[0][ks][3], sh0);
            As[1][ks][0] = hmul2u(A[1][ks][0], sl1);
            As[1][ks][1] = hmul2u(A[1][ks][1], sh1);
            As[1][ks][2] = hmul2u(A[1][ks][2], sl1);
            As[1][ks][3] = hmul2u(A[1][ks][3], sh1);
        }

        #pragma unroll
        for (int nt = 0; nt < 4; nt++) {
            const int nb = nt * 8 + g;
            #pragma unroll
            for (int ks = 0; ks < 2; ks++) {
                const int kpb = c * 16 + ks * 8;
                const uint32_t b0 = sW[(kpb + tig) * SWS2 + nb];
                const uint32_t b1 = sW[(kpb + tig + 4) * SWS2 + nb];
                mma16n8k16(m[nt][0], As[0][ks], b0, b1);
                mma16n8k16(m[nt][1], As[1][ks], b0, b1);
            }
        }
    }

    // ---- epilogue: pair-exchange -> one float4 RED per thread per strip ----
    #pragma unroll
    for (int nt = 0; nt < 4; nt++) {
        const int colb = nt * 8 + 2 * (tig & ~1);
        const bool odd = (tig & 1);
        #pragma unroll
        for (int s = 0; s < 2; s++) {
            float s0 = __shfl_xor_sync(0xffffffffu, odd ? m[nt][s][0] : m[nt][s][2], 1);
            float s1 = __shfl_xor_sync(0xffffffffu, odd ? m[nt][s][1] : m[nt][s][3], 1);
            int drow = odd ? dhi[s] : dlo[s];
            float4 val = odd ? make_float4(s0, s1, m[nt][s][2], m[nt][s][3])
                             : make_float4(m[nt][s][0], m[nt][s][1], s0, s1);
            if (drow >= 0)
                atomicAdd((float4*)(acc + (size_t)drow * FD + colb), val);
        }
    }
}

// ---------------------------------------------------------------------------
// Root kernel via mma.sync m16n8k16.f16, COALESCED epilogue (R15 version):
//   acc[n,:] = sigmoid(acc[n,:] + x[n,:] @ Wr + b)
// ---------------------------------------------------------------------------
#define ROOT_BLK_I ((N_I + 255) / 256)   // 391
#define ROOT_BLK_O ((N_O + 255) / 256)   // 196

#define RSF 36                                  // result-tile stride (floats)
#define R_OFF_SB   0                            // sB: 16*SWS2 u32 = 2560B
#define R_OFF_BIAS (16 * SWS2 * 4)              // 2560
#define R_OFF_WARP (R_OFF_BIAS + 128)           // 2688
#define R_WARP_BYTES (32 * RSF * 4)             // 4608 (sx 2560B overlays this)
#define ROOT_SMEM  (R_OFF_WARP + 8 * R_WARP_BYTES)  // 39552

__global__ __launch_bounds__(256) void root_mma(
    const float* __restrict__ xI, const float* __restrict__ WrI, const float* __restrict__ bI,
    const float* __restrict__ xO, const float* __restrict__ WrO, const float* __restrict__ bO)
{
    extern __shared__ char rsmem[];
    uint32_t* sB = (uint32_t*)(rsmem + R_OFF_SB);
    float*    sb = (float*)   (rsmem + R_OFF_BIAS);

    const int rel = (blockIdx.x >= ROOT_BLK_I) ? 1 : 0;
    const float* __restrict__ x  = rel ? xO  : xI;
    const float* __restrict__ Wr = rel ? WrO : WrI;
    const float* __restrict__ b  = rel ? bO  : bI;
    float* acc = rel ? g_acc_o : g_acc_i;
    const int N = rel ? N_O : N_I;
    const int base = (rel ? (blockIdx.x - ROOT_BLK_I) : blockIdx.x) * 256;

    const int t = threadIdx.x;
    const int warp = t >> 5;
    const int lane = t & 31;
    const int g   = lane >> 2;
    const int tig = lane & 3;

    // stage Wr (B matrix) + bias (grid-stride over 512 entries)
    for (int idx = t; idx < 512; idx += 256) {
        int kp = idx >> 5, n = idx & 31;
        sB[kp * SWS2 + n] = packh2(Wr[(2 * kp) * FD + n], Wr[(2 * kp + 1) * FD + n]);
    }
    if (t < FD) sb[t] = b[t];
    __syncthreads();

    const int rowbase = base + warp * 32;
    float*    sf = (float*)(rsmem + R_OFF_WARP + warp * R_WARP_BYTES);  // [32][36]
    uint32_t* sx = (uint32_t*)sf;                                       // overlay [32][20]
    const int h2 = lane >> 4;
    const int p2 = lane & 15;

    // ---- stage x rows as half2 (contiguous rows, coalesced 128B) ----
    #pragma unroll 4
    for (int rr = 0; rr < 16; rr++) {
        const int row = 2 * rr + h2;
        const int gn = rowbase + row;
        float2 v = make_float2(0.f, 0.f);
        if (gn < N) v = *(const float2*)(x + (size_t)gn * FD + 2 * p2);
        sx[row * SXS2 + p2] = packh2(v.x, v.y);
    }
    __syncwarp();

    // ---- A fragments: 2 strips x 2 k16-steps ----
    uint32_t A[2][2][4];
    #pragma unroll
    for (int s = 0; s < 2; s++) {
        #pragma unroll
        for (int ks = 0; ks < 2; ks++) {
            const int rb = s * 16 + g, kp = ks * 8;
            A[s][ks][0] = sx[rb * SXS2 + kp + tig];
            A[s][ks][1] = sx[(rb + 8) * SXS2 + kp + tig];
            A[s][ks][2] = sx[rb * SXS2 + kp + tig + 4];
            A[s][ks][3] = sx[(rb + 8) * SXS2 + kp + tig + 4];
        }
    }
    __syncwarp();   // sx fully consumed; sf may now be overwritten

    float m[4][2][4] = {};
    #pragma unroll
    for (int nt = 0; nt < 4; nt++) {
        const int nb = nt * 8 + g;
        #pragma unroll
        for (int ks = 0; ks < 2; ks++) {
            const uint32_t b0 = sB[(ks * 8 + tig) * SWS2 + nb];
            const uint32_t b1 = sB[(ks * 8 + tig + 4) * SWS2 + nb];
            mma16n8k16(m[nt][0], A[0][ks], b0, b1);
            mma16n8k16(m[nt][1], A[1][ks], b0, b1);
        }
    }

    // ---- stage fragments into result tile ----
    #pragma unroll
    for (int nt = 0; nt < 4; nt++) {
        const int colb = nt * 8 + 2 * tig;
        #pragma unroll
        for (int s = 0; s < 2; s++) {
            const int r0 = s * 16 + g, r1 = r0 + 8;
            *(float2*)(sf + r0 * RSF + colb) = make_float2(m[nt][s][0], m[nt][s][1]);
            *(float2*)(sf + r1 * RSF + colb) = make_float2(m[nt][s][2], m[nt][s][3]);
        }
    }
    __syncwarp();

    // ---- coalesced RMW: lane covers (row 4*r8 + l>>3, cols (l&7)*4 .. +3) ----
    const int rloc = lane >> 3;
    const int cq   = (lane & 7) * 4;
    const float4 bq = ((const float4*)sb)[lane & 7];
    #pragma unroll
    for (int r8 = 0; r8 < 8; r8++) {
        const int row = r8 * 4 + rloc;
        const int gn = rowbase + row;
        if (gn < N) {
            float4* p = (float4*)(acc + (size_t)gn * FD + cq);
            float4 av = *p;
            const float4 mv = *(const float4*)(sf + row * RSF + cq);
            av.x = sigmoidf(av.x + mv.x + bq.x);
            av.y = sigmoidf(av.y + mv.y + bq.y);
            av.z = sigmoidf(av.z + mv.z + bq.z);
            av.w = sigmoidf(av.w + mv.w + bq.w);
            *p = av;
        }
    }
}

// ---------------------------------------------------------------------------
// Layer-2 edge kernel (f_out = 1), 8 edges per warp, 2 per octet (MLP=2)
// ---------------------------------------------------------------------------
__global__ __launch_bounds__(256) void edge2_kernel(
    const int*   __restrict__ src,
    const int*   __restrict__ dst,
    const float* __restrict__ eattr,
    const float* __restrict__ Wm2,
    const float* __restrict__ bm2)
{
    __shared__ float4 sW4[EAD * 8];
    __shared__ float4 sb4[8];

    const int t = threadIdx.x;
    if (t < EAD * 8) sW4[t] = ((const float4*)Wm2)[t];
    if (t < 8)       sb4[t] = ((const float4*)bm2)[t];
    __syncthreads();

    const int gwarp = (blockIdx.x * 256 + t) >> 5;
    const int lane  = t & 31;
    const int q     = lane & 7;
    const int e1    = gwarp * 8 + (lane >> 3);
    const int e2    = e1 + 4;
    if (e1 >= NE) return;
    const bool v2 = (e2 < NE);

    const int s1 = src[e1];
    const int s2 = v2 ? src[e2] : 0;
    const float4 h1 = ((const float4*)g_acc_o)[s1 * 8 + q];
    const float4 h2 = ((const float4*)g_acc_o)[s2 * 8 + q];
    const float4 a10 = ((const float4*)eattr)[e1 * 2 + 0];
    const float4 a11 = ((const float4*)eattr)[e1 * 2 + 1];
    const float4 a20 = v2 ? ((const float4*)eattr)[e2 * 2 + 0] : make_float4(0,0,0,0);
    const float4 a21 = v2 ? ((const float4*)eattr)[e2 * 2 + 1] : make_float4(0,0,0,0);
    const float ea1[EAD] = {a10.x, a10.y, a10.z, a10.w, a11.x, a11.y, a11.z, a11.w};
    const float ea2[EAD] = {a20.x, a20.y, a20.z, a20.w, a21.x, a21.y, a21.z, a21.w};

    float4 c1 = sb4[q], c2 = sb4[q];
    #pragma unroll
    for (int a = 0; a < EAD; a++) {
        const float4 w = sW4[a * 8 + q];
        c1.x = fmaf(ea1[a], w.x, c1.x);  c2.x = fmaf(ea2[a], w.x, c2.x);
        c1.y = fmaf(ea1[a], w.y, c1.y);  c2.y = fmaf(ea2[a], w.y, c2.y);
        c1.z = fmaf(ea1[a], w.z, c1.z);  c2.z = fmaf(ea2[a], w.z, c2.z);
        c1.w = fmaf(ea1[a], w.w, c1.w);  c2.w = fmaf(ea2[a], w.w, c2.w);
    }

    float p1 = h1.x * c1.x + h1.y * c1.y + h1.z * c1.z + h1.w * c1.w;
    float p2 = h2.x * c2.x + h2.y * c2.y + h2.z * c2.z + h2.w * c2.w;
    p1 += __shfl_down_sync(0xffffffffu, p1, 4, 8);
    p2 += __shfl_down_sync(0xffffffffu, p2, 4, 8);
    p1 += __shfl_down_sync(0xffffffffu, p1, 2, 8);
    p2 += __shfl_down_sync(0xffffffffu, p2, 2, 8);
    p1 += __shfl_down_sync(0xffffffffu, p1, 1, 8);
    p2 += __shfl_down_sync(0xffffffffu, p2, 1, 8);

    if (q == 0) {
        atomicAdd(&g_acc2[dst[e1]], p1);
        if (v2) atomicAdd(&g_acc2[dst[e2]], p2);
    }
}

// ---------------------------------------------------------------------------
// Output: out[n] = sigmoid(acc2[n] + h_indivi[n,:] @ Wr2 + b2)   (warp per node)
// ---------------------------------------------------------------------------
__global__ __launch_bounds__(256) void out_kernel(
    const float* __restrict__ Wr2,
    const float* __restrict__ b2,
    float* __restrict__ out)
{
    const int t = threadIdx.x;
    const int n = (blockIdx.x * 256 + t) >> 5;
    const int lane = t & 31;
    if (n >= N_I) return;

    float p = g_acc_i[n * FD + lane] * __ldg(&Wr2[lane]);
    #pragma unroll
    for (int off = 16; off; off >>= 1)
        p += __shfl_down_sync(0xffffffffu, p, off);

    if (lane == 0)
        out[n] = sigmoidf(p + g_acc2[n] + __ldg(&b2[0]));
}

// ---------------------------------------------------------------------------
extern "C" void kernel_launch(void* const* d_in, const int* in_sizes, int n_in,
                              void* d_out, int out_size)
{
    const float* x_indivi = (const float*)d_in[0];
    const float* x_org    = (const float*)d_in[1];
    const int*   src_oi   = (const int*)  d_in[2];
    const int*   dst_oi   = (const int*)  d_in[3];
    const float* ea_oi    = (const float*)d_in[4];
    const int*   src_io   = (const int*)  d_in[5];
    const int*   dst_io   = (const int*)  d_in[6];
    const float* ea_io    = (const float*)d_in[7];
    const float* Wm_oi    = (const float*)d_in[8];
    const float* bm_oi    = (const float*)d_in[9];
    const float* Wr_oi    = (const float*)d_in[10];
    const float* b_oi     = (const float*)d_in[11];
    const float* Wm_io    = (const float*)d_in[12];
    const float* bm_io    = (const float*)d_in[13];
    const float* Wr_io    = (const float*)d_in[14];
    const float* b_io     = (const float*)d_in[15];
    const float* Wm2      = (const float*)d_in[16];
    const float* bm2      = (const float*)d_in[17];
    const float* Wr2      = (const float*)d_in[18];
    const float* b2       = (const float*)d_in[19];
    float* out = (float*)d_out;

    cudaFuncSetAttribute(edge_mma_kernel,
                         cudaFuncAttributeMaxDynamicSharedMemorySize, SMEM_DYN);

    zero_kernel<<<512, 256>>>();
    // rel0 (org->indivi): src=x_org, acc=g_acc_i. rel1 (indivi->org): src=x_indivi, acc=g_acc_o.
    edge_mma_kernel<<<2 * EDGE_CTAS_PER_REL, 256, SMEM_DYN>>>(
        x_org,    src_oi, dst_oi, ea_oi, Wm_oi, bm_oi,
        x_indivi, src_io, dst_io, ea_io, Wm_io, bm_io);
    root_mma<<<ROOT_BLK_I + ROOT_BLK_O, 256, ROOT_SMEM>>>(
        x_indivi, Wr_oi, b_oi, x_org, Wr_io, b_io);
    edge2_kernel<<<(NE + 8 * 8 - 1) / (8 * 8), 256>>>(src_oi, dst_oi, ea_oi, Wm2, bm2);
    out_kernel<<<(N_I * 32 + 255) / 256, 256>>>(Wr2, b2, out);
}